// round 2
// baseline (speedup 1.0000x reference)
#include <cuda_runtime.h>
#include <cstdint>

// ---------------------------------------------------------------------------
// ConvLSTMBlock: x(4,16,128,128,32) --conv3x3 s2--> xz(64,64,64,256)
// then 16-step recurrence: z = xz[t] + conv3x3_s1(h, U) + b; Keras gates;
// y[b,t] = BN(h_new).  All fp32.
// ---------------------------------------------------------------------------

#define Bn   4
#define Tn   16
#define HW   64            // output spatial 64x64
#define Fch  64
#define NCH  256           // 4F
#define MPIX_IN  (Bn*Tn*HW*HW)   // 262144  (input-conv GEMM M)
#define MPIX_ST  (Bn*HW*HW)      // 16384   (per-step GEMM M)

// Scratch (module-load allocated; no cudaMalloc anywhere)
__device__ float g_xz[(size_t)MPIX_IN * NCH];     // 256 MiB
__device__ float g_h[2][(size_t)MPIX_ST * Fch];   // double-buffered hidden
__device__ float g_c[(size_t)MPIX_ST * Fch];      // cell state (in-place safe)

__device__ __forceinline__ float hsig(float v) {
    return fminf(fmaxf(0.2f * v + 0.5f, 0.0f), 1.0f);
}

// ---------------------------------------------------------------------------
// Zero initial state (h[0], c)
// ---------------------------------------------------------------------------
__global__ void zero_state_kernel() {
    int i = blockIdx.x * blockDim.x + threadIdx.x;
    if (i < MPIX_ST * Fch) { g_h[0][i] = 0.0f; g_c[i] = 0.0f; }
}

// ---------------------------------------------------------------------------
// Input conv: implicit GEMM  M=262144, N=256, K=288 (9 taps x 32ch)
// stride 2, SAME: pad_before = 0 (pad_total = 1), so iy = 2*oy + ky.
// Tile: 64 (M) x 256 (N), 256 threads, 8x8 per thread.
// Bias b folded into g_xz here.
// ---------------------------------------------------------------------------
__global__ __launch_bounds__(256) void conv_in_kernel(
    const float* __restrict__ x, const float* __restrict__ W,
    const float* __restrict__ bias)
{
    __shared__ float As[64][32];
    __shared__ float Bs[32][256];

    const int m0  = blockIdx.x * 64;
    const int tid = threadIdx.x;
    const int tm  = tid >> 5;     // 0..7
    const int tn  = tid & 31;     // 0..31

    float acc[8][8];
    #pragma unroll
    for (int i = 0; i < 8; i++)
        #pragma unroll
        for (int j = 0; j < 8; j++) acc[i][j] = 0.0f;

    for (int chunk = 0; chunk < 9; chunk++) {
        const int ky = chunk / 3, kx = chunk % 3;
        // --- load A tile: 64 pixels x 32 input channels of this tap ---
        #pragma unroll
        for (int j = 0; j < 8; j++) {
            int p     = (tid >> 5) + j * 8;       // 0..63
            int pixel = m0 + p;
            int img   = pixel >> 12;              // /4096
            int rem   = pixel & 4095;
            int oy    = rem >> 6, ox = rem & 63;
            int iy    = 2 * oy + ky;
            int ix    = 2 * ox + kx;
            float v   = 0.0f;
            if (iy < 128 && ix < 128)
                v = __ldg(&x[(((size_t)img * 128 + iy) * 128 + ix) * 32 + (tid & 31)]);
            As[p][tid & 31] = v;
        }
        // --- load B tile: 32 x 256 weights (row-major, coalesced) ---
        const float* Wp = W + (size_t)chunk * 32 * 256;
        #pragma unroll
        for (int it = 0; it < 32; it++) {
            int idx = tid + it * 256;
            Bs[idx >> 8][idx & 255] = __ldg(&Wp[idx]);
        }
        __syncthreads();

        #pragma unroll 8
        for (int k = 0; k < 32; k++) {
            float a[8], bb[8];
            #pragma unroll
            for (int i = 0; i < 8; i++) a[i] = As[tm + 8 * i][k];
            #pragma unroll
            for (int j = 0; j < 8; j++) bb[j] = Bs[k][tn + 32 * j];
            #pragma unroll
            for (int i = 0; i < 8; i++)
                #pragma unroll
                for (int j = 0; j < 8; j++) acc[i][j] = fmaf(a[i], bb[j], acc[i][j]);
        }
        __syncthreads();
    }

    // epilogue: g_xz[pixel][n] = acc + b[n]
    #pragma unroll
    for (int i = 0; i < 8; i++) {
        int pixel  = m0 + tm + 8 * i;
        float* dst = g_xz + (size_t)pixel * NCH;
        #pragma unroll
        for (int j = 0; j < 8; j++) {
            int n  = tn + 32 * j;
            dst[n] = acc[i][j] + bias[n];
        }
    }
}

// ---------------------------------------------------------------------------
// One LSTM step: z = xz[t] + conv3x3_s1(h_prev, U); gates; c,h update; BN out.
// Implicit GEMM M=16384, N=256, K=576 (9 taps x 64ch, 18 chunks of 32).
// acc initialized from g_xz (bias already folded).
// Gate layout: n in [0,64)=i, [64,128)=f, [128,192)=g, [192,256)=o, so thread
// columns j and j+2/j+4/j+6 share feature channel fc = tn + 32*(j&1).
// ---------------------------------------------------------------------------
__global__ __launch_bounds__(256) void lstm_step_kernel(
    const float* __restrict__ U,
    const float* __restrict__ gamma_, const float* __restrict__ beta_,
    const float* __restrict__ mmean,  const float* __restrict__ mvar,
    float* __restrict__ out, int t, int parity)
{
    __shared__ float As[64][32];
    __shared__ float Bs[32][256];

    const float* __restrict__ hprev = g_h[parity];
    float* __restrict__ hnext       = g_h[parity ^ 1];

    const int m0  = blockIdx.x * 64;
    const int tid = threadIdx.x;
    const int tm  = tid >> 5;
    const int tn  = tid & 31;

    float acc[8][8];
    // init accumulators from precomputed xz[t] (+bias)
    #pragma unroll
    for (int i = 0; i < 8; i++) {
        int pixel = m0 + tm + 8 * i;           // b*4096 + yx
        int bimg  = pixel >> 12;
        int yx    = pixel & 4095;
        const float* src = g_xz + ((size_t)(bimg * Tn + t) * 4096 + yx) * NCH;
        #pragma unroll
        for (int j = 0; j < 8; j++) acc[i][j] = src[tn + 32 * j];
    }

    for (int chunk = 0; chunk < 18; chunk++) {
        const int tap = chunk >> 1;
        const int ky  = tap / 3, kx = tap % 3;
        const int c   = ((chunk & 1) << 5) + (tid & 31);   // 0..63
        // --- A tile: 64 pixels of h_prev, this tap, 32 channels ---
        #pragma unroll
        for (int j = 0; j < 8; j++) {
            int p     = (tid >> 5) + j * 8;
            int pixel = m0 + p;
            int bimg  = pixel >> 12;
            int yx    = pixel & 4095;
            int y     = yx >> 6, xx = yx & 63;
            int iy    = y + ky - 1;
            int ix    = xx + kx - 1;
            float v   = 0.0f;
            if ((unsigned)iy < 64u && (unsigned)ix < 64u)
                v = hprev[(((size_t)bimg * 64 + iy) * 64 + ix) * 64 + c];
            As[p][tid & 31] = v;
        }
        // --- B tile: U rows [chunk*32, chunk*32+32) x 256 ---
        const float* Up = U + (size_t)chunk * 32 * 256;
        #pragma unroll
        for (int it = 0; it < 32; it++) {
            int idx = tid + it * 256;
            Bs[idx >> 8][idx & 255] = __ldg(&Up[idx]);
        }
        __syncthreads();

        #pragma unroll 8
        for (int k = 0; k < 32; k++) {
            float a[8], bb[8];
            #pragma unroll
            for (int i = 0; i < 8; i++) a[i] = As[tm + 8 * i][k];
            #pragma unroll
            for (int j = 0; j < 8; j++) bb[j] = Bs[k][tn + 32 * j];
            #pragma unroll
            for (int i = 0; i < 8; i++)
                #pragma unroll
                for (int j = 0; j < 8; j++) acc[i][j] = fmaf(a[i], bb[j], acc[i][j]);
        }
        __syncthreads();
    }

    // ---- fused gate + state + BN epilogue (all in registers) ----
    float sc[2], bt[2], mn[2];
    #pragma unroll
    for (int jj = 0; jj < 2; jj++) {
        int fc = tn + 32 * jj;
        sc[jj] = gamma_[fc] * rsqrtf(mvar[fc] + 1e-3f);
        bt[jj] = beta_[fc];
        mn[jj] = mmean[fc];
    }
    #pragma unroll
    for (int i = 0; i < 8; i++) {
        int pixel = m0 + tm + 8 * i;
        int bimg  = pixel >> 12;
        int yx    = pixel & 4095;
        #pragma unroll
        for (int jj = 0; jj < 2; jj++) {
            int fc   = tn + 32 * jj;
            float zi = acc[i][jj];
            float zf = acc[i][jj + 2];
            float zg = acc[i][jj + 4];
            float zo = acc[i][jj + 6];
            size_t sidx = (size_t)pixel * Fch + fc;
            float cp = g_c[sidx];
            float ig = hsig(zi), fg = hsig(zf), og = hsig(zo);
            float cn = fg * cp + ig * tanhf(zg);
            float hn = og * tanhf(cn);
            g_c[sidx]   = cn;
            hnext[sidx] = hn;
            out[((size_t)(bimg * Tn + t) * 4096 + yx) * Fch + fc] =
                (hn - mn[jj]) * sc[jj] + bt[jj];
        }
    }
}

// ---------------------------------------------------------------------------
extern "C" void kernel_launch(void* const* d_in, const int* in_sizes, int n_in,
                              void* d_out, int out_size)
{
    const float* x      = (const float*)d_in[0];
    const float* W      = (const float*)d_in[1];
    const float* U      = (const float*)d_in[2];
    const float* b      = (const float*)d_in[3];
    const float* gamma_ = (const float*)d_in[4];
    const float* beta_  = (const float*)d_in[5];
    const float* mmean  = (const float*)d_in[6];
    const float* mvar   = (const float*)d_in[7];
    float* out          = (float*)d_out;

    zero_state_kernel<<<(MPIX_ST * Fch + 255) / 256, 256>>>();
    conv_in_kernel<<<MPIX_IN / 64, 256>>>(x, W, b);
    for (int t = 0; t < Tn; t++) {
        lstm_step_kernel<<<MPIX_ST / 64, 256>>>(U, gamma_, beta_, mmean, mvar,
                                                out, t, t & 1);
    }
}

// round 5
// speedup vs baseline: 1.0516x; 1.0516x over previous
#include <cuda_runtime.h>
#include <cstdint>

// ---------------------------------------------------------------------------
// ConvLSTMBlock: x(4,16,128,128,32) --conv3x3 s2--> xz(64,64,64,256)
// 16-step recurrence: z = xz[t] + conv3x3_s1(h, U) + b; Keras gates; BN out.
// All fp32; GEMM inner loops use packed fma.rn.f32x2 (FFMA2, 2 FMA/issue).
// ---------------------------------------------------------------------------

#define Bn   4
#define Tn   16
#define HW   64
#define Fch  64
#define NCH  256
#define MPIX_IN  (Bn*Tn*HW*HW)   // 262144
#define MPIX_ST  (Bn*HW*HW)      // 16384

typedef unsigned long long u64;

__device__ float g_xz[(size_t)MPIX_IN * NCH];     // 256 MiB scratch
__device__ float g_h[2][(size_t)MPIX_ST * Fch];
__device__ float g_c[(size_t)MPIX_ST * Fch];

__device__ __forceinline__ void ffma2(u64& d, u64 a, u64 b) {
    asm("fma.rn.f32x2 %0, %1, %2, %0;" : "+l"(d) : "l"(a), "l"(b));
}
__device__ __forceinline__ float2 unpack2(u64 u) {
    float2 v; asm("mov.b64 {%0, %1}, %2;" : "=f"(v.x), "=f"(v.y) : "l"(u));
    return v;
}
__device__ __forceinline__ float hsig(float v) {
    return fminf(fmaxf(0.2f * v + 0.5f, 0.0f), 1.0f);
}

__global__ void zero_state_kernel() {
    int i = blockIdx.x * blockDim.x + threadIdx.x;
    if (i < MPIX_ST * Fch) { g_h[0][i] = 0.0f; g_c[i] = 0.0f; }
}

// ---------------------------------------------------------------------------
// Input conv: implicit GEMM M=262144, N=256, K=288 (9 taps x 32ch), stride 2.
// Tile 64(M) x 256(N), 256 threads, per thread 8 m x 4 n-pairs (FFMA2).
// ---------------------------------------------------------------------------
__global__ __launch_bounds__(256, 2) void conv_in_kernel(
    const float* __restrict__ x, const float* __restrict__ W,
    const float* __restrict__ bias)
{
    __shared__ float As2[64][64];   // [pixel][2*c] value duplicated -> FFMA2 operand
    __shared__ float Bs[32][256];   // [c][n]

    const int m0  = blockIdx.x * 64;
    const int tid = threadIdx.x;
    const int tm  = tid >> 5;       // warp id 0..7
    const int tn  = tid & 31;       // lane

    u64 acc[8][4];
    #pragma unroll
    for (int i = 0; i < 8; i++)
        #pragma unroll
        for (int g = 0; g < 4; g++) acc[i][g] = 0ull;

    for (int chunk = 0; chunk < 9; chunk++) {
        const int ky = chunk / 3, kx = chunk % 3;
        // A tile: 64 pixels x 32 channels of this tap, stored duplicated
        #pragma unroll
        for (int j = 0; j < 8; j++) {
            int p     = tm + j * 8;
            int pixel = m0 + p;
            int img   = pixel >> 12;
            int rem   = pixel & 4095;
            int oy    = rem >> 6, ox = rem & 63;
            int iy    = 2 * oy + ky;
            int ix    = 2 * ox + kx;
            float v   = 0.0f;
            if (iy < 128 && ix < 128)
                v = __ldg(&x[(((size_t)img * 128 + iy) * 128 + ix) * 32 + tn]);
            *reinterpret_cast<float2*>(&As2[p][2 * tn]) = make_float2(v, v);
        }
        // B tile: 32 x 256 weights
        const float* Wp = W + (size_t)chunk * 32 * 256;
        #pragma unroll
        for (int it = 0; it < 32; it++) {
            int idx = tid + it * 256;
            Bs[idx >> 8][idx & 255] = __ldg(&Wp[idx]);
        }
        __syncthreads();

        #pragma unroll 8
        for (int k = 0; k < 32; k++) {
            u64 bv[4];
            #pragma unroll
            for (int g = 0; g < 4; g++)
                bv[g] = *reinterpret_cast<const u64*>(&Bs[k][2 * tn + 64 * g]);
            #pragma unroll
            for (int i = 0; i < 8; i++) {
                u64 av = *reinterpret_cast<const u64*>(&As2[tm + 8 * i][2 * k]);
                #pragma unroll
                for (int g = 0; g < 4; g++) ffma2(acc[i][g], av, bv[g]);
            }
        }
        __syncthreads();
    }

    #pragma unroll
    for (int i = 0; i < 8; i++) {
        int pixel  = m0 + tm + 8 * i;
        float* dst = g_xz + (size_t)pixel * NCH;
        #pragma unroll
        for (int g = 0; g < 4; g++) {
            int n    = 2 * tn + 64 * g;
            float2 v = unpack2(acc[i][g]);
            v.x += bias[n];
            v.y += bias[n + 1];
            *reinterpret_cast<float2*>(&dst[n]) = v;
        }
    }
}

// ---------------------------------------------------------------------------
// One LSTM step: implicit GEMM M=16384, N=256, K=576 (18 chunks of 32),
// acc seeded from xz[t]; fused gates + cell + BN epilogue.
// n-pair layout: n = 2*tn + 64*g + {0,1}; g = gate (i,f,c,o); fc = 2*tn+{0,1}.
// ---------------------------------------------------------------------------
__global__ __launch_bounds__(256, 2) void lstm_step_kernel(
    const float* __restrict__ U,
    const float* __restrict__ gamma_, const float* __restrict__ beta_,
    const float* __restrict__ mmean,  const float* __restrict__ mvar,
    float* __restrict__ out, int t, int parity)
{
    __shared__ float As2[64][64];
    __shared__ float Bs[32][256];

    const float* __restrict__ hprev = g_h[parity];
    float* __restrict__ hnext       = g_h[parity ^ 1];

    const int m0  = blockIdx.x * 64;
    const int tid = threadIdx.x;
    const int tm  = tid >> 5;
    const int tn  = tid & 31;

    u64 acc[8][4];
    #pragma unroll
    for (int i = 0; i < 8; i++) {
        int pixel = m0 + tm + 8 * i;
        int bimg  = pixel >> 12;
        int yx    = pixel & 4095;
        const float* src = g_xz + ((size_t)(bimg * Tn + t) * 4096 + yx) * NCH;
        #pragma unroll
        for (int g = 0; g < 4; g++)
            acc[i][g] = *reinterpret_cast<const u64*>(&src[2 * tn + 64 * g]);
    }

    for (int chunk = 0; chunk < 18; chunk++) {
        const int tap = chunk >> 1;
        const int ky  = tap / 3, kx = tap % 3;
        const int c   = ((chunk & 1) << 5) + tn;    // 0..63
        #pragma unroll
        for (int j = 0; j < 8; j++) {
            int p     = tm + j * 8;
            int pixel = m0 + p;
            int bimg  = pixel >> 12;
            int yx    = pixel & 4095;
            int y     = yx >> 6, xx = yx & 63;
            int iy    = y + ky - 1;
            int ix    = xx + kx - 1;
            float v   = 0.0f;
            if ((unsigned)iy < 64u && (unsigned)ix < 64u)
                v = hprev[(((size_t)bimg * 64 + iy) * 64 + ix) * 64 + c];
            *reinterpret_cast<float2*>(&As2[p][2 * tn]) = make_float2(v, v);
        }
        const float* Up = U + (size_t)chunk * 32 * 256;
        #pragma unroll
        for (int it = 0; it < 32; it++) {
            int idx = tid + it * 256;
            Bs[idx >> 8][idx & 255] = __ldg(&Up[idx]);
        }
        __syncthreads();

        #pragma unroll 8
        for (int k = 0; k < 32; k++) {
            u64 bv[4];
            #pragma unroll
            for (int g = 0; g < 4; g++)
                bv[g] = *reinterpret_cast<const u64*>(&Bs[k][2 * tn + 64 * g]);
            #pragma unroll
            for (int i = 0; i < 8; i++) {
                u64 av = *reinterpret_cast<const u64*>(&As2[tm + 8 * i][2 * k]);
                #pragma unroll
                for (int g = 0; g < 4; g++) ffma2(acc[i][g], av, bv[g]);
            }
        }
        __syncthreads();
    }

    // ---- fused gate + state + BN epilogue (float2 lanes fc = 2tn, 2tn+1) ----
    float2 sc, bt, mn;
    {
        int fc = 2 * tn;
        sc.x = gamma_[fc]     * rsqrtf(mvar[fc]     + 1e-3f);
        sc.y = gamma_[fc + 1] * rsqrtf(mvar[fc + 1] + 1e-3f);
        bt = *reinterpret_cast<const float2*>(&beta_[fc]);
        mn = *reinterpret_cast<const float2*>(&mmean[fc]);
    }
    #pragma unroll
    for (int i = 0; i < 8; i++) {
        int pixel = m0 + tm + 8 * i;
        int bimg  = pixel >> 12;
        int yx    = pixel & 4095;
        float2 zi = unpack2(acc[i][0]);
        float2 zf = unpack2(acc[i][1]);
        float2 zg = unpack2(acc[i][2]);
        float2 zo = unpack2(acc[i][3]);
        size_t sidx = (size_t)pixel * Fch + 2 * tn;
        float2 cp = *reinterpret_cast<const float2*>(&g_c[sidx]);
        float2 cn, hn, ov;
        cn.x = hsig(zf.x) * cp.x + hsig(zi.x) * tanhf(zg.x);
        cn.y = hsig(zf.y) * cp.y + hsig(zi.y) * tanhf(zg.y);
        hn.x = hsig(zo.x) * tanhf(cn.x);
        hn.y = hsig(zo.y) * tanhf(cn.y);
        ov.x = (hn.x - mn.x) * sc.x + bt.x;
        ov.y = (hn.y - mn.y) * sc.y + bt.y;
        *reinterpret_cast<float2*>(&g_c[sidx])   = cn;
        *reinterpret_cast<float2*>(&hnext[sidx]) = hn;
        *reinterpret_cast<float2*>(
            &out[((size_t)(bimg * Tn + t) * 4096 + yx) * Fch + 2 * tn]) = ov;
    }
}

// ---------------------------------------------------------------------------
extern "C" void kernel_launch(void* const* d_in, const int* in_sizes, int n_in,
                              void* d_out, int out_size)
{
    const float* x      = (const float*)d_in[0];
    const float* W      = (const float*)d_in[1];
    const float* U      = (const float*)d_in[2];
    const float* b      = (const float*)d_in[3];
    const float* gamma_ = (const float*)d_in[4];
    const float* beta_  = (const float*)d_in[5];
    const float* mmean  = (const float*)d_in[6];
    const float* mvar   = (const float*)d_in[7];
    float* out          = (float*)d_out;

    zero_state_kernel<<<(MPIX_ST * Fch + 255) / 256, 256>>>();
    conv_in_kernel<<<MPIX_IN / 64, 256>>>(x, W, b);
    for (int t = 0; t < Tn; t++) {
        lstm_step_kernel<<<MPIX_ST / 64, 256>>>(U, gamma_, beta_, mmean, mvar,
                                                out, t, t & 1);
    }
}